// round 15
// baseline (speedup 1.0000x reference)
#include <cuda_runtime.h>
#include <cuda_fp16.h>
#include <cstdint>

// ---------------------------------------------------------------------------
// CoMA forward: 3x (ChebConv K=6 -> ReLU -> Pool) -> Linear(25024,128) -> ReLU
//               -> Linear(128,2)
// Node-major fp16 features, fp32 accumulation. Per-layer persistent Chebyshev
// kernel (grid barrier between steps), smem ping-pong for own-node T_{k-2}.
// Layer-0 rows padded 96->128 halves so LPN=8/CH=2 fits 4 blocks/SM (occ 50%).
// ---------------------------------------------------------------------------

#define BATCH 32
#define KORD 6
#define CAP 32

#define N0 50000
#define N1 12500
#define N2 3125
#define N3 782
#define E0 300000
#define E1 75000
#define E2 18750

#define NDEG (N0 + N1 + N2)
#define B_OFF0 ((size_t)0)
#define B_OFF1 ((size_t)N0 * CAP)
#define B_OFF2 ((size_t)(N0 + N1) * CAP)
#define DEG_OFF0 0
#define DEG_OFF1 N0
#define DEG_OFF2 (N0 + N1)

#define W0H 128   // layer-0 padded row width in halves (logical 96)

#define SLOTH 6500000
__device__ __align__(16) __half g_h[(size_t)7 * SLOTH + 64];
__device__ float g_enc[4096];
__device__ __align__(16) int2 g_bpair[(size_t)NDEG * CAP + 8];
__device__ int g_deg[NDEG];
__device__ int g_bar[3][16];

struct HP6 { __half* p[6]; };

// ---------------------------------------------------------------------------
__global__ void k_init()
{
    int i = blockIdx.x * blockDim.x + threadIdx.x;
    if (i < NDEG) g_deg[i] = 0;
    if (i < 4096) g_enc[i] = 0.f;
    if (i < 48) ((int*)g_bar)[i] = 0;
}

__global__ void k_bucket_all(const int* __restrict__ e0, const float* __restrict__ nm0,
                             const int* __restrict__ e1, const float* __restrict__ nm1,
                             const int* __restrict__ e2, const float* __restrict__ nm2)
{
    int e = blockIdx.x * blockDim.x + threadIdx.x;
    const int* rows; const float* nm; int idx, E; int doff; size_t boff;
    if (e < E0)            { idx = e;           rows = e0; nm = nm0; E = E0; doff = DEG_OFF0; boff = B_OFF0; }
    else if (e < E0 + E1)  { idx = e - E0;      rows = e1; nm = nm1; E = E1; doff = DEG_OFF1; boff = B_OFF1; }
    else if (e < E0+E1+E2) { idx = e - E0 - E1; rows = e2; nm = nm2; E = E2; doff = DEG_OFF2; boff = B_OFF2; }
    else return;
    int r = rows[idx];
    int c = rows[idx + E];
    int d = atomicAdd(&g_deg[doff + r], 1);
    if (d < CAP)
        g_bpair[boff + (size_t)r * CAP + d] = make_int2(c, __float_as_int(nm[idx]));
}

// ---------------------------------------------------------------------------
// fused: transpose x (B,N0,3) fp32 -> (N0, W0H) fp16 (pad zeros) AND pad buckets
#define TBLOCKS 1563   // ceil(N0/32)
__global__ void k_transpad(const float* __restrict__ x, __half* __restrict__ xt)
{
    if (blockIdx.x < TBLOCKS) {
        __shared__ float s[32][100];
        int n0  = blockIdx.x * 32;
        int tid = threadIdx.x;
        for (int i = tid; i < 32 * 96; i += 256) {
            int b = i / 96, r = i % 96;
            int nl = r / 3, c = r % 3;
            int n = n0 + nl;
            if (n < N0) s[nl][b * 3 + c] = x[((size_t)b * N0 + n) * 3 + c];
        }
        __syncthreads();
        uint4* out4 = (uint4*)xt;
        for (int i = tid; i < 32 * 16; i += 256) {   // 16 uint4 per padded row
            int nl = i / 16, v = i % 16;
            int n = n0 + nl;
            if (n >= N0) continue;
            uint4 o;
            if (v < 12) {
                const float* sp = &s[nl][v * 8];
                ((__half2*)&o)[0] = __floats2half2_rn(sp[0], sp[1]);
                ((__half2*)&o)[1] = __floats2half2_rn(sp[2], sp[3]);
                ((__half2*)&o)[2] = __floats2half2_rn(sp[4], sp[5]);
                ((__half2*)&o)[3] = __floats2half2_rn(sp[6], sp[7]);
            } else {
                o = make_uint4(0, 0, 0, 0);
            }
            out4[(size_t)n * 16 + v] = o;
        }
    } else {
        int i = (blockIdx.x - TBLOCKS) * 256 + threadIdx.x;   // flat node id
        if (i >= NDEG) return;
        int d  = min(g_deg[i], CAP);
        int dp = min((d + 3) & ~3, CAP);
        size_t row = (size_t)i * CAP;
        for (int j = d; j < dp; j++) g_bpair[row + j] = make_int2(0, 0);
    }
}

// ---------------------------------------------------------------------------
// persistent per-layer Chebyshev kernel; 4-edge batched gathers; own-node
// prev (T_{k-2}) served from a 2-deep smem ping-pong buffer.
template <int LPN, int CH, int NPB, int PASSES, int MB>
__global__ void __launch_bounds__(256, MB)
k_cheb_layer(HP6 T, int N, const int2* __restrict__ bp_base,
             const int* __restrict__ deg, int* bar)
{
    constexpr int W = LPN * CH;
    static_assert(PASSES * (256 / LPN) >= NPB, "passes");
    __shared__ uint4 sping[2][NPB * W];
    __shared__ int   sdeg[NPB];

    int tid = threadIdx.x;
    int nb  = blockIdx.x * NPB;
    int nn  = N - nb;
    if (nn > NPB) nn = NPB;
    if (nn < 0) nn = 0;

    for (int i = tid; i < nn; i += 256) {
        int d = min(deg[nb + i], CAP);
        sdeg[i] = min((d + 3) & ~3, CAP);
    }
    __syncthreads();

    for (int k = 1; k < KORD; k++) {
        const __half* src = T.p[k - 1];
        __half*       dst = T.p[k];
        float scale = (k == 1) ? 1.f : 2.f;
        const uint4* s4 = (const uint4*)src;
        uint4* sp_buf = sping[k & 1];

#pragma unroll
        for (int p = 0; p < PASSES; p++) {
            int ln = p * (256 / LPN) + tid / LPN;
            int c4 = tid % LPN;
            if (ln < nn) {
                int node = nb + ln;
                int dpad = sdeg[ln];

                float2 acc[CH][4];
                if (k == 1) {
#pragma unroll
                    for (int t = 0; t < CH; t++)
#pragma unroll
                        for (int q = 0; q < 4; q++) acc[t][q] = make_float2(0.f, 0.f);
                } else if (k == 2) {
                    const uint4* p4 = (const uint4*)T.p[0] + (size_t)node * W + c4;
#pragma unroll
                    for (int t = 0; t < CH; t++) {
                        uint4 pv = p4[t * LPN];
#pragma unroll
                        for (int q = 0; q < 4; q++) {
                            float2 v = __half22float2(((const __half2*)&pv)[q]);
                            acc[t][q] = make_float2(-v.x, -v.y);
                        }
                    }
                } else {
#pragma unroll
                    for (int t = 0; t < CH; t++) {
                        uint4 pv = sp_buf[ln * W + t * LPN + c4];
#pragma unroll
                        for (int q = 0; q < 4; q++) {
                            float2 v = __half22float2(((const __half2*)&pv)[q]);
                            acc[t][q] = make_float2(-v.x, -v.y);
                        }
                    }
                }

                const int4* mrow = (const int4*)(bp_base + (size_t)node * CAP);
                for (int j = 0; j < dpad; j += 4) {
                    int4 ma = mrow[j / 2];
                    int4 mb = mrow[j / 2 + 1];
                    const uint4* sa = s4 + (size_t)ma.x * W + c4;
                    const uint4* sb = s4 + (size_t)ma.z * W + c4;
                    const uint4* sc = s4 + (size_t)mb.x * W + c4;
                    const uint4* sd = s4 + (size_t)mb.z * W + c4;
                    uint4 va[CH], vb[CH], vc[CH], vd[CH];
#pragma unroll
                    for (int t = 0; t < CH; t++) va[t] = sa[t * LPN];
#pragma unroll
                    for (int t = 0; t < CH; t++) vb[t] = sb[t * LPN];
#pragma unroll
                    for (int t = 0; t < CH; t++) vc[t] = sc[t * LPN];
#pragma unroll
                    for (int t = 0; t < CH; t++) vd[t] = sd[t * LPN];
                    float f0 = __int_as_float(ma.y) * scale;
                    float f1 = __int_as_float(ma.w) * scale;
                    float f2 = __int_as_float(mb.y) * scale;
                    float f3 = __int_as_float(mb.w) * scale;
#pragma unroll
                    for (int t = 0; t < CH; t++) {
#pragma unroll
                        for (int q = 0; q < 4; q++) {
                            float2 a = __half22float2(((const __half2*)&va[t])[q]);
                            float2 b = __half22float2(((const __half2*)&vb[t])[q]);
                            float2 c = __half22float2(((const __half2*)&vc[t])[q]);
                            float2 d = __half22float2(((const __half2*)&vd[t])[q]);
                            acc[t][q].x += f0 * a.x + f1 * b.x + f2 * c.x + f3 * d.x;
                            acc[t][q].y += f0 * a.y + f1 * b.y + f2 * c.y + f3 * d.y;
                        }
                    }
                }

                uint4* d4 = (uint4*)dst + (size_t)node * W + c4;
#pragma unroll
                for (int t = 0; t < CH; t++) {
                    uint4 o;
#pragma unroll
                    for (int q = 0; q < 4; q++)
                        ((__half2*)&o)[q] = __floats2half2_rn(acc[t][q].x, acc[t][q].y);
                    d4[t * LPN] = o;
                    if (k <= KORD - 3)
                        sp_buf[ln * W + t * LPN + c4] = o;
                }
            }
        }

        if (k < KORD - 1) {
            __threadfence();
            __syncthreads();
            if (tid == 0) {
                int t = atomicAdd(&bar[2 * k], 1);
                if (t == (int)gridDim.x - 1) {
                    atomicExch(&bar[2 * k + 1], 1);
                } else {
                    while (*(volatile int*)&bar[2 * k + 1] == 0) __nanosleep(64);
                }
                __threadfence();
            }
            __syncthreads();
        }
    }
}

// ---------------------------------------------------------------------------
// fused pool + ChebConv output projection + ReLU. STRIDEH = row stride in
// halves of the T buffers (padded for layer 0).
struct TPtrs { const __half* T[KORD]; };

template <int FIN, int FOUT, int STRIDEH>
__global__ void k_pool_cheb(TPtrs tp, const float* __restrict__ w,
                            const float* __restrict__ bias,
                            const int* __restrict__ pcols,
                            const float* __restrict__ pvals,
                            __half* __restrict__ out, int n_out)
{
    constexpr int FINP = (FIN % 2 == 0) ? FIN + 1 : FIN;
    constexpr int NO   = FOUT / 4;

    __shared__ __align__(16) float sW[KORD * FIN * FOUT];
    __shared__ float sT[KORD][32 * FINP];

    int tid = threadIdx.x;
    for (int i = tid; i < KORD * FIN * FOUT; i += 128) sW[i] = w[i];

    int b  = tid & 31;
    int og = tid >> 5;

    float bz[NO], acc[NO];
#pragma unroll
    for (int j = 0; j < NO; j++) { bz[j] = bias[og * NO + j]; acc[j] = 0.f; }

    int r = blockIdx.x;
    if (r >= n_out) return;

#pragma unroll
    for (int j3 = 0; j3 < 3; j3++) {
        int   col = pcols[r * 3 + j3];
        float pv  = pvals[r * 3 + j3];
        __syncthreads();
#pragma unroll
        for (int k = 0; k < KORD; k++) {
            const __half* src = tp.T[k] + (size_t)col * STRIDEH;
            for (int i = tid; i < 32 * FIN; i += 128) {
                int bb = i / FIN, ii = i - bb * FIN;
                sT[k][bb * FINP + ii] = __half2float(src[i]);
            }
        }
        __syncthreads();

        float y[NO];
#pragma unroll
        for (int j = 0; j < NO; j++) y[j] = bz[j];

#pragma unroll
        for (int k = 0; k < KORD; k++) {
            float rT[FIN];
#pragma unroll
            for (int i = 0; i < FIN; i++) rT[i] = sT[k][b * FINP + i];
#pragma unroll
            for (int i = 0; i < FIN; i++) {
                const float* wrow = &sW[(k * FIN + i) * FOUT + og * NO];
#pragma unroll
                for (int j = 0; j < NO; j += 4) {
                    float4 w4 = *(const float4*)(wrow + j);
                    y[j + 0] += rT[i] * w4.x;
                    y[j + 1] += rT[i] * w4.y;
                    y[j + 2] += rT[i] * w4.z;
                    y[j + 3] += rT[i] * w4.w;
                }
            }
        }
#pragma unroll
        for (int j = 0; j < NO; j++) acc[j] += pv * fmaxf(y[j], 0.f);
    }

    __half* o = out + ((size_t)r * 32 + b) * FOUT + og * NO;
#pragma unroll
    for (int j = 0; j < NO; j++) o[j] = __float2half(acc[j]);
}

// ---------------------------------------------------------------------------
// encoder split-K GEMM (4 nodes per block)
__global__ void k_enc(const __half* __restrict__ h, const float* __restrict__ wenc,
                      float* __restrict__ enc, int N)
{
    __shared__ float sH[4 * 32 * 32];
    int tid = threadIdx.x;
    int n0  = blockIdx.x * 4;
    int nn  = min(4, N - n0);
    for (int i = tid; i < nn * 1024; i += 256)
        sH[i] = __half2float(h[(size_t)n0 * 1024 + i]);
    __syncthreads();

    int z  = tid & 127;
    int bh = tid >> 7;
    float acc[16];
#pragma unroll
    for (int j = 0; j < 16; j++) acc[j] = 0.f;

    for (int n = 0; n < nn; n++) {
#pragma unroll
        for (int f = 0; f < 32; f++) {
            float wv = wenc[((size_t)(n0 + n) * 32 + f) * 128 + z];
#pragma unroll
            for (int j = 0; j < 16; j++)
                acc[j] += wv * sH[n * 1024 + (bh * 16 + j) * 32 + f];
        }
    }
#pragma unroll
    for (int j = 0; j < 16; j++)
        atomicAdd(&enc[(bh * 16 + j) * 128 + z], acc[j]);
}

__global__ void k_final(const float* __restrict__ enc, const float* __restrict__ benc,
                        const float* __restrict__ wcls, const float* __restrict__ bcls,
                        float* __restrict__ out)
{
    int t = threadIdx.x;
    if (t >= 64) return;
    int b = t >> 1, c = t & 1;
    float a = bcls[c];
    for (int z = 0; z < 128; z++) {
        float e = fmaxf(enc[b * 128 + z] + benc[z], 0.f);
        a += e * wcls[z * 2 + c];
    }
    out[b * 2 + c] = a;
}

// ---------------------------------------------------------------------------
extern "C" void kernel_launch(void* const* d_in, const int* in_sizes, int n_in,
                              void* d_out, int out_size)
{
    const float* x;
    const int*   edge[3];
    const float* norm[3];
    const int*   pidx[3];
    const float* pval[3];
    const float *w[3], *bb[3], *wenc, *benc, *wcls, *bcls;

    if (in_sizes[3] == 150000) {
        x = (const float*)d_in[0];
        edge[0] = (const int*)d_in[1];  norm[0] = (const float*)d_in[2];
        edge[1] = (const int*)d_in[3];  norm[1] = (const float*)d_in[4];
        edge[2] = (const int*)d_in[5];  norm[2] = (const float*)d_in[6];
        pidx[0] = (const int*)d_in[7];  pval[0] = (const float*)d_in[8];
        pidx[1] = (const int*)d_in[9];  pval[1] = (const float*)d_in[10];
        pidx[2] = (const int*)d_in[11]; pval[2] = (const float*)d_in[12];
    } else {
        x = (const float*)d_in[0];
        edge[0] = (const int*)d_in[1];  norm[0] = (const float*)d_in[2];
        pidx[0] = (const int*)d_in[3];  pval[0] = (const float*)d_in[4];
        edge[1] = (const int*)d_in[5];  norm[1] = (const float*)d_in[6];
        pidx[1] = (const int*)d_in[7];  pval[1] = (const float*)d_in[8];
        edge[2] = (const int*)d_in[9];  norm[2] = (const float*)d_in[10];
        pidx[2] = (const int*)d_in[11]; pval[2] = (const float*)d_in[12];
    }
    w[0]  = (const float*)d_in[13]; bb[0] = (const float*)d_in[14];
    w[1]  = (const float*)d_in[15]; bb[1] = (const float*)d_in[16];
    w[2]  = (const float*)d_in[17]; bb[2] = (const float*)d_in[18];
    wenc  = (const float*)d_in[19]; benc  = (const float*)d_in[20];
    wcls  = (const float*)d_in[21]; bcls  = (const float*)d_in[22];

    __half* base = nullptr;
    cudaGetSymbolAddress((void**)&base, g_h);
    float* enc = nullptr;
    cudaGetSymbolAddress((void**)&enc, g_enc);
    int2* bpair = nullptr;
    cudaGetSymbolAddress((void**)&bpair, g_bpair);
    int* deg = nullptr;
    cudaGetSymbolAddress((void**)&deg, g_deg);
    int* bar = nullptr;
    cudaGetSymbolAddress((void**)&bar, g_bar);

    __half* H0 = base;
    __half* H1 = base + (size_t)SLOTH;
    __half* T1 = base + (size_t)2 * SLOTH;
    __half* T2 = base + (size_t)3 * SLOTH;
    __half* T3 = base + (size_t)4 * SLOTH;
    __half* T4 = base + (size_t)5 * SLOTH;
    __half* T5 = base + (size_t)6 * SLOTH;

    // ---- setup: init -> buckets -> {transpose(padded) + pad} ----
    k_init<<<(NDEG + 255) / 256, 256>>>();
    k_bucket_all<<<(E0 + E1 + E2 + 255) / 256, 256>>>(edge[0], norm[0],
                                                      edge[1], norm[1],
                                                      edge[2], norm[2]);
    k_transpad<<<TBLOCKS + (NDEG + 255) / 256, 256>>>(x, H0);

    // ---- layer 0: N0, padded W=16 uint4 (128 halves), Fout=16 ----
    {
        HP6 T; T.p[0] = H0; T.p[1] = T1; T.p[2] = T2; T.p[3] = T3; T.p[4] = T4; T.p[5] = T5;
        k_cheb_layer<8, 2, 85, 3, 4><<<(N0 + 84) / 85, 256>>>(T, N0, bpair + B_OFF0,
                                                              deg + DEG_OFF0, bar + 0);
        TPtrs tp; tp.T[0] = H0; tp.T[1] = T1; tp.T[2] = T2; tp.T[3] = T3; tp.T[4] = T4; tp.T[5] = T5;
        k_pool_cheb<3, 16, W0H><<<N1, 128>>>(tp, w[0], bb[0],
                                             pidx[0] + (size_t)N1 * 3, pval[0], H1, N1);
    }
    // ---- layer 1: N1, W=64 uint4 (512 halves), Fout=16 ----
    {
        HP6 T; T.p[0] = H1; T.p[1] = T1; T.p[2] = T2; T.p[3] = T3; T.p[4] = T4; T.p[5] = T5;
        k_cheb_layer<32, 2, 22, 3, 4><<<(N1 + 21) / 22, 256>>>(T, N1, bpair + B_OFF1,
                                                               deg + DEG_OFF1, bar + 16);
        TPtrs tp; tp.T[0] = H1; tp.T[1] = T1; tp.T[2] = T2; tp.T[3] = T3; tp.T[4] = T4; tp.T[5] = T5;
        k_pool_cheb<16, 16, 512><<<N2, 128>>>(tp, w[1], bb[1],
                                              pidx[1] + (size_t)N2 * 3, pval[1], H0, N2);
    }
    // ---- layer 2: N2, W=64 uint4, Fout=32 ----
    {
        HP6 T; T.p[0] = H0; T.p[1] = T1; T.p[2] = T2; T.p[3] = T3; T.p[4] = T4; T.p[5] = T5;
        k_cheb_layer<32, 2, 6, 1, 4><<<(N2 + 5) / 6, 256>>>(T, N2, bpair + B_OFF2,
                                                            deg + DEG_OFF2, bar + 32);
        TPtrs tp; tp.T[0] = H0; tp.T[1] = T1; tp.T[2] = T2; tp.T[3] = T3; tp.T[4] = T4; tp.T[5] = T5;
        k_pool_cheb<16, 32, 512><<<N3, 128>>>(tp, w[2], bb[2],
                                              pidx[2] + (size_t)N3 * 3, pval[2], H1, N3);
    }
    // ---- encoder + classifier ----
    k_enc<<<(N3 + 3) / 4, 256>>>(H1, wenc, enc, N3);
    k_final<<<1, 64>>>(enc, benc, wcls, bcls, (float*)d_out);
}